// round 1
// baseline (speedup 1.0000x reference)
#include <cuda_runtime.h>
#include <math.h>

#define DIM      128
#define HEADS    8
#define DH       16
#define FFD      512
#define DEPTH    4
#define EPSV     1e-5f
#define NTHREADS 256

// Intermediate between channel stack and temporal stack: [64 batch][64 patch][128]
__device__ float g_mid[64 * 64 * DIM];

struct StackParams {
    const float *Wq, *Wk, *Wv, *Wo, *bo;
    const float *g1, *be1, *g2, *be2;
    const float *W1, *bf1, *W2, *bf2;
};

__device__ __forceinline__ float gelu_tanh(float x) {
    // jax.nn.gelu approximate=True (tanh form)
    float x3 = x * x * x;
    return 0.5f * x * (1.0f + tanhf(0.7978845608028654f * (x + 0.044715f * x3)));
}

// ---------------------------------------------------------------------------
// C[N x 128] (stride ldc) (+)= A[N x K] (stride lda, SMEM) @ W[K x 128-slice]
// (stride ldw, GMEM) [+ bias] [gelu]
// Thread map: tx = tid&31 -> float4 column group (128 cols), ty = tid>>5,
// TM=8 tokens per thread (covers up to 64 tokens in ONE pass -> W read once).
// ---------------------------------------------------------------------------
template<int N, int K, bool ACC, bool GELU_, bool BIAS>
__device__ __forceinline__ void gemm128(
    const float* __restrict__ A, int lda,
    const float* __restrict__ W, int ldw,
    const float* __restrict__ bias,
    float* __restrict__ C, int ldc, int tid)
{
    const int tx = tid & 31;
    const int ty = tid >> 5;

    float4 acc[8];
#pragma unroll
    for (int i = 0; i < 8; i++) acc[i] = make_float4(0.f, 0.f, 0.f, 0.f);

    int cidx[8];
#pragma unroll
    for (int i = 0; i < 8; i++) {
        int c = ty + i * 8;
        cidx[i] = (c < N) ? c : (N - 1);   // clamp; garbage computed, store guarded
    }

    const float* Wp = W + tx * 4;

#pragma unroll 4
    for (int kk = 0; kk < K; kk++) {
        float4 w = *(const float4*)(Wp + (size_t)kk * ldw);
#pragma unroll
        for (int i = 0; i < 8; i++) {
            float a = A[cidx[i] * lda + kk];   // warp-uniform SMEM broadcast
            acc[i].x += a * w.x;
            acc[i].y += a * w.y;
            acc[i].z += a * w.z;
            acc[i].w += a * w.w;
        }
    }

    float4 b4 = make_float4(0.f, 0.f, 0.f, 0.f);
    if (BIAS) b4 = *(const float4*)(bias + tx * 4);

#pragma unroll
    for (int i = 0; i < 8; i++) {
        int c = ty + i * 8;
        if (c < N) {
            float4 r = acc[i];
            if (BIAS) { r.x += b4.x; r.y += b4.y; r.z += b4.z; r.w += b4.w; }
            if (GELU_) {
                r.x = gelu_tanh(r.x); r.y = gelu_tanh(r.y);
                r.z = gelu_tanh(r.z); r.w = gelu_tanh(r.w);
            }
            float* dst = C + c * ldc + tx * 4;
            if (ACC) {
                dst[0] += r.x; dst[1] += r.y; dst[2] += r.z; dst[3] += r.w;
            } else {
                *(float4*)dst = r;
            }
        }
    }
}

// ---------------------------------------------------------------------------
template<int N>
__device__ __forceinline__ void layernorm(
    const float* __restrict__ src, float* __restrict__ dst,
    const float* __restrict__ g, const float* __restrict__ b, int tid)
{
    int lane = tid & 31, wid = tid >> 5;
    float4 g4 = *(const float4*)(g + lane * 4);
    float4 b4 = *(const float4*)(b + lane * 4);
    for (int c = wid; c < N; c += 8) {
        float4 x = *(const float4*)(src + c * DIM + lane * 4);
        float s = x.x + x.y + x.z + x.w;
#pragma unroll
        for (int o = 16; o; o >>= 1) s += __shfl_xor_sync(0xffffffffu, s, o);
        float m = s * (1.0f / DIM);
        float dx = x.x - m, dy = x.y - m, dz = x.z - m, dw = x.w - m;
        float v = dx * dx + dy * dy + dz * dz + dw * dw;
#pragma unroll
        for (int o = 16; o; o >>= 1) v += __shfl_xor_sync(0xffffffffu, v, o);
        float rs = rsqrtf(v * (1.0f / DIM) + EPSV);
        float4 r;
        r.x = dx * rs * g4.x + b4.x;
        r.y = dy * rs * g4.y + b4.y;
        r.z = dz * rs * g4.z + b4.z;
        r.w = dw * rs * g4.w + b4.w;
        *(float4*)(dst + c * DIM + lane * 4) = r;
    }
}

// softmax over the 16-feature head dim, then * dh^-0.5 (= 0.25)
template<int N>
__device__ __forceinline__ void softmax_feat(float* __restrict__ q, int tid)
{
    int lane = tid & 31, wid = tid >> 5;
    for (int c = wid; c < N; c += 8) {
        float4 x = *(const float4*)(q + c * DIM + lane * 4);
        float m = fmaxf(fmaxf(x.x, x.y), fmaxf(x.z, x.w));
        m = fmaxf(m, __shfl_xor_sync(0xffffffffu, m, 1));
        m = fmaxf(m, __shfl_xor_sync(0xffffffffu, m, 2));
        float4 e;
        e.x = expf(x.x - m); e.y = expf(x.y - m);
        e.z = expf(x.z - m); e.w = expf(x.w - m);
        float s = e.x + e.y + e.z + e.w;
        s += __shfl_xor_sync(0xffffffffu, s, 1);
        s += __shfl_xor_sync(0xffffffffu, s, 2);
        float sc = 0.25f / s;
        e.x *= sc; e.y *= sc; e.z *= sc; e.w *= sc;
        *(float4*)(q + c * DIM + lane * 4) = e;
    }
}

// softmax over the sequence dim (per feature column)
template<int N>
__device__ __forceinline__ void softmax_seq(float* __restrict__ k, int tid)
{
    if (tid < DIM) {
        float* p = k + tid;
        float m = -1e30f;
        for (int c = 0; c < N; c++) m = fmaxf(m, p[c * DIM]);
        float s = 0.f;
        for (int c = 0; c < N; c++) {
            float e = expf(p[c * DIM] - m);
            p[c * DIM] = e;
            s += e;
        }
        float inv = 1.0f / s;
        for (int c = 0; c < N; c++) p[c * DIM] *= inv;
    }
}

// ctx[h][d][e] = sum_c k[c][h*16+d] * v[c][h*16+e]
template<int N>
__device__ __forceinline__ void compute_ctx(
    const float* __restrict__ k, const float* __restrict__ v,
    float* __restrict__ ctx, int tid)
{
    for (int o = tid; o < HEADS * DH * DH; o += NTHREADS) {
        int hh = o >> 8, d = (o >> 4) & 15, e = o & 15;
        const float* kp = k + hh * DH + d;
        const float* vp = v + hh * DH + e;
        float a = 0.f;
        for (int c = 0; c < N; c++) a += kp[c * DIM] * vp[c * DIM];
        ctx[o] = a;
    }
}

// o[c][h*16+e] = sum_d q[c][h*16+d] * ctx[h][d][e]
template<int N>
__device__ __forceinline__ void apply_ctx(
    const float* __restrict__ q, const float* __restrict__ ctx,
    float* __restrict__ o, int tid)
{
    int tx = tid & 31, ty = tid >> 5;
    int hh = tx >> 2;
    int ecol = (tx & 3) * 4;
    for (int c = ty; c < N; c += 8) {
        float4 acc = make_float4(0.f, 0.f, 0.f, 0.f);
        const float* qp = q + c * DIM + hh * DH;
        const float* cp = ctx + hh * DH * DH + ecol;
#pragma unroll
        for (int d = 0; d < DH; d++) {
            float qv = qp[d];
            float4 cv = *(const float4*)(cp + d * DH);
            acc.x += qv * cv.x; acc.y += qv * cv.y;
            acc.z += qv * cv.z; acc.w += qv * cv.w;
        }
        *(float4*)(o + c * DIM + tx * 4) = acc;
    }
}

template<int N>
__device__ __forceinline__ void mean_rows(
    const float* __restrict__ h, float* __restrict__ out, int tid)
{
    if (tid < DIM) {
        float s = 0.f;
        for (int c = 0; c < N; c++) s += h[c * DIM + tid];
        out[tid] = s * (1.0f / N);
    }
}

// ---------------------------------------------------------------------------
// One CTA = one sequence. Full 4-layer stack in SMEM.
// SMEM slabs: h | s1 | s2 | s3 | s4 | s5 | ctx(2048)
//   attn: xn->s1, q->s2, k->s3, v->s4, o->s1 (reuse)
//   ff:   xn2->s5, t[N][512] spans s1..s4 (contiguous)
// MODE 0: channel stack, load from x [B,E,C,P], write mean -> g_mid[s]
// MODE 1: temporal stack, load from g_mid, write mean -> gout[b]
// ---------------------------------------------------------------------------
template<int N, int MODE>
__global__ void __launch_bounds__(NTHREADS, 1)
stack_kernel(const float* __restrict__ xin, float* __restrict__ gout, StackParams P)
{
    extern __shared__ float sm[];
    float* h   = sm;
    float* s1  = sm + N * DIM;
    float* s2  = s1 + N * DIM;
    float* s3  = s2 + N * DIM;
    float* s4  = s3 + N * DIM;
    float* s5  = s4 + N * DIM;
    float* ctx = s5 + N * DIM;

    const int tid = threadIdx.x;

    // -------- load sequence into h --------
    if (MODE == 0) {
        int s = blockIdx.x;
        int b = s >> 6, p = s & 63;
        const float* xb = xin + (size_t)b * DIM * 62 * 64 + p;
        for (int i = tid; i < N * DIM; i += NTHREADS) {
            int c = i >> 7, e = i & 127;
            h[i] = xb[(e * 62 + c) * 64];
        }
    } else {
        const float* xb = g_mid + (size_t)blockIdx.x * N * DIM;
        for (int i = tid; i < N * DIM; i += NTHREADS) h[i] = xb[i];
    }
    __syncthreads();

    for (int l = 0; l < DEPTH; l++) {
        const float* Wq  = P.Wq  + l * DIM * DIM;
        const float* Wk  = P.Wk  + l * DIM * DIM;
        const float* Wv  = P.Wv  + l * DIM * DIM;
        const float* Wo  = P.Wo  + l * DIM * DIM;
        const float* bo  = P.bo  + l * DIM;
        const float* g1  = P.g1  + l * DIM;
        const float* be1 = P.be1 + l * DIM;
        const float* g2  = P.g2  + l * DIM;
        const float* be2 = P.be2 + l * DIM;
        const float* W1  = P.W1  + l * DIM * FFD;
        const float* bf1 = P.bf1 + l * FFD;
        const float* W2  = P.W2  + l * FFD * DIM;
        const float* bf2 = P.bf2 + l * DIM;

        // ---- attention ----
        layernorm<N>(h, s1, g1, be1, tid);
        __syncthreads();

        gemm128<N, DIM, false, false, false>(s1, DIM, Wq, DIM, nullptr, s2, DIM, tid);
        gemm128<N, DIM, false, false, false>(s1, DIM, Wk, DIM, nullptr, s3, DIM, tid);
        gemm128<N, DIM, false, false, false>(s1, DIM, Wv, DIM, nullptr, s4, DIM, tid);
        __syncthreads();

        softmax_feat<N>(s2, tid);
        softmax_seq<N>(s3, tid);
        __syncthreads();

        compute_ctx<N>(s3, s4, ctx, tid);
        __syncthreads();

        apply_ctx<N>(s2, ctx, s1, tid);
        __syncthreads();

        gemm128<N, DIM, true, false, true>(s1, DIM, Wo, DIM, bo, h, DIM, tid);
        __syncthreads();

        // ---- feed-forward ----
        layernorm<N>(h, s5, g2, be2, tid);
        __syncthreads();

#pragma unroll
        for (int j = 0; j < 4; j++) {
            gemm128<N, DIM, false, true, true>(s5, DIM,
                                               W1 + j * DIM, FFD,
                                               bf1 + j * DIM,
                                               s1 + j * DIM, FFD, tid);
        }
        __syncthreads();

        gemm128<N, FFD, true, false, true>(s1, FFD, W2, DIM, bf2, h, DIM, tid);
        __syncthreads();
    }

    // -------- mean over tokens --------
    if (MODE == 0) {
        mean_rows<N>(h, g_mid + (size_t)blockIdx.x * DIM, tid);
    } else {
        mean_rows<N>(h, gout + (size_t)blockIdx.x * DIM, tid);
    }
}

// ---------------------------------------------------------------------------
static StackParams mk_params(void* const* d_in, int base)
{
    StackParams p;
    p.Wq  = (const float*)d_in[base + 0];
    p.Wk  = (const float*)d_in[base + 1];
    p.Wv  = (const float*)d_in[base + 2];
    p.Wo  = (const float*)d_in[base + 3];
    p.bo  = (const float*)d_in[base + 4];
    p.g1  = (const float*)d_in[base + 5];
    p.be1 = (const float*)d_in[base + 6];
    p.g2  = (const float*)d_in[base + 7];
    p.be2 = (const float*)d_in[base + 8];
    p.W1  = (const float*)d_in[base + 9];
    p.bf1 = (const float*)d_in[base + 10];
    p.W2  = (const float*)d_in[base + 11];
    p.bf2 = (const float*)d_in[base + 12];
    return p;
}

extern "C" void kernel_launch(void* const* d_in, const int* in_sizes, int n_in,
                              void* d_out, int out_size)
{
    (void)in_sizes; (void)n_in; (void)out_size;

    const float* x = (const float*)d_in[0];
    StackParams Pc = mk_params(d_in, 1);
    StackParams Pt = mk_params(d_in, 14);

    const int SMEM_A = (6 * 62 * DIM + HEADS * DH * DH) * (int)sizeof(float); // 198656
    const int SMEM_B = (6 * 64 * DIM + HEADS * DH * DH) * (int)sizeof(float); // 204800

    cudaFuncSetAttribute(stack_kernel<62, 0>,
                         cudaFuncAttributeMaxDynamicSharedMemorySize, SMEM_A);
    cudaFuncSetAttribute(stack_kernel<64, 1>,
                         cudaFuncAttributeMaxDynamicSharedMemorySize, SMEM_B);

    // channel stack: 64 batches * 64 patches sequences of length 62
    stack_kernel<62, 0><<<4096, NTHREADS, SMEM_A>>>(x, nullptr, Pc);
    // temporal stack: 64 sequences of length 64 (reads g_mid, writes d_out)
    stack_kernel<64, 1><<<64, NTHREADS, SMEM_B>>>(nullptr, (float*)d_out, Pt);
}

// round 2
// speedup vs baseline: 1.3350x; 1.3350x over previous
#include <cuda_runtime.h>
#include <math.h>
#include <stdint.h>

#define DIM      128
#define HEADS    8
#define DH       16
#define FFD      512
#define DEPTH    4
#define EPSV     1e-5f
#define NTHREADS 512
#define NWARPS   16
#define KCHUNK   16
#define WBUF_ELEMS (2 * KCHUNK * DIM)   // double-buffered 16x128 chunk

// Intermediate between channel stack and temporal stack: [64 batch][64 patch][128]
__device__ float g_mid[64 * 64 * DIM];

struct StackParams {
    const float *Wq, *Wk, *Wv, *Wo, *bo;
    const float *g1, *be1, *g2, *be2;
    const float *W1, *bf1, *W2, *bf2;
};

__device__ __forceinline__ float gelu_tanh(float x) {
    float x3 = x * x * x;
    return 0.5f * x * (1.0f + tanhf(0.7978845608028654f * (x + 0.044715f * x3)));
}

// ---------------- cp.async helpers ----------------
__device__ __forceinline__ void cp16(void* dst, const void* src) {
    uint32_t d = (uint32_t)__cvta_generic_to_shared(dst);
    asm volatile("cp.async.ca.shared.global [%0], [%1], 16;" :: "r"(d), "l"(src));
}
__device__ __forceinline__ void cp_commit() {
    asm volatile("cp.async.commit_group;");
}
__device__ __forceinline__ void cp_wait0() {
    asm volatile("cp.async.wait_group 0;");
}

// Stage one KCHUNK x 128 chunk of W (row stride ldw) into smem.
// 512 threads, each copies exactly one float4. No residue.
__device__ __forceinline__ void stage_chunk(float* __restrict__ dst,
                                            const float* __restrict__ src,
                                            int ldw, int tid)
{
    int r  = tid >> 5;    // 0..15 rows
    int c4 = tid & 31;    // float4 column
    cp16(dst + r * DIM + c4 * 4, src + (size_t)r * ldw + c4 * 4);
}

// ---------------------------------------------------------------------------
// C[N x 128] (stride ldc) (+)= A[N x K](smem, stride lda) @ W[K x 128-slice]
// (gmem, stride ldw) [+bias] [gelu].  W double-buffered through smem via
// cp.async; copy of chunk c+1 overlaps compute of chunk c.
// Map: tx=lane -> float4 col group; wy=warp -> tokens wy + i*16, TM=4.
// Ends with __syncthreads() (protects wbuf + outputs for the caller).
// ---------------------------------------------------------------------------
template<int N, int K, bool ACC, bool GELU_, bool BIAS>
__device__ __forceinline__ void gemm_staged(
    const float* __restrict__ A, int lda,
    const float* __restrict__ W, int ldw,
    const float* __restrict__ bias,
    float* __restrict__ C, int ldc,
    float* __restrict__ wbuf, int tid)
{
    const int tx = tid & 31;
    const int wy = tid >> 5;

    float4 acc[4];
#pragma unroll
    for (int i = 0; i < 4; i++) acc[i] = make_float4(0.f, 0.f, 0.f, 0.f);

    int cidx[4];
#pragma unroll
    for (int i = 0; i < 4; i++) {
        int c = wy + i * NWARPS;
        cidx[i] = (c < N) ? c : (N - 1);   // clamp; garbage computed, store guarded
    }

    constexpr int NCH = K / KCHUNK;

    stage_chunk(wbuf, W, ldw, tid);
    cp_commit();

    for (int ch = 0; ch < NCH; ch++) {
        cp_wait0();
        __syncthreads();
        if (ch + 1 < NCH) {
            stage_chunk(wbuf + ((ch + 1) & 1) * (KCHUNK * DIM),
                        W + (size_t)(ch + 1) * KCHUNK * ldw, ldw, tid);
            cp_commit();
        }
        const float* wb = wbuf + (ch & 1) * (KCHUNK * DIM);
        const int kbase = ch * KCHUNK;
#pragma unroll
        for (int kk = 0; kk < KCHUNK; kk++) {
            float4 w = *(const float4*)(wb + kk * DIM + tx * 4);
#pragma unroll
            for (int i = 0; i < 4; i++) {
                float a = A[cidx[i] * lda + kbase + kk];  // warp-uniform broadcast
                acc[i].x += a * w.x;
                acc[i].y += a * w.y;
                acc[i].z += a * w.z;
                acc[i].w += a * w.w;
            }
        }
    }

    float4 b4 = make_float4(0.f, 0.f, 0.f, 0.f);
    if (BIAS) b4 = *(const float4*)(bias + tx * 4);

#pragma unroll
    for (int i = 0; i < 4; i++) {
        int c = wy + i * NWARPS;
        if (c < N) {
            float4 r = acc[i];
            if (BIAS) { r.x += b4.x; r.y += b4.y; r.z += b4.z; r.w += b4.w; }
            if (GELU_) {
                r.x = gelu_tanh(r.x); r.y = gelu_tanh(r.y);
                r.z = gelu_tanh(r.z); r.w = gelu_tanh(r.w);
            }
            float* dst = C + (size_t)c * ldc + tx * 4;
            if (ACC) {
                dst[0] += r.x; dst[1] += r.y; dst[2] += r.z; dst[3] += r.w;
            } else {
                *(float4*)dst = r;
            }
        }
    }
    __syncthreads();
}

// ---------------------------------------------------------------------------
template<int N>
__device__ __forceinline__ void layernorm(
    const float* __restrict__ src, float* __restrict__ dst,
    const float* __restrict__ g, const float* __restrict__ b, int tid)
{
    int lane = tid & 31, wid = tid >> 5;
    float4 g4 = *(const float4*)(g + lane * 4);
    float4 b4 = *(const float4*)(b + lane * 4);
    for (int c = wid; c < N; c += NWARPS) {
        float4 x = *(const float4*)(src + c * DIM + lane * 4);
        float s = x.x + x.y + x.z + x.w;
#pragma unroll
        for (int o = 16; o; o >>= 1) s += __shfl_xor_sync(0xffffffffu, s, o);
        float m = s * (1.0f / DIM);
        float dx = x.x - m, dy = x.y - m, dz = x.z - m, dw = x.w - m;
        float v = dx * dx + dy * dy + dz * dz + dw * dw;
#pragma unroll
        for (int o = 16; o; o >>= 1) v += __shfl_xor_sync(0xffffffffu, v, o);
        float rs = rsqrtf(v * (1.0f / DIM) + EPSV);
        float4 r;
        r.x = dx * rs * g4.x + b4.x;
        r.y = dy * rs * g4.y + b4.y;
        r.z = dz * rs * g4.z + b4.z;
        r.w = dw * rs * g4.w + b4.w;
        *(float4*)(dst + c * DIM + lane * 4) = r;
    }
}

// softmax over the 16-feature head dim, then * dh^-0.5 (= 0.25)
template<int N>
__device__ __forceinline__ void softmax_feat(float* __restrict__ q, int tid)
{
    int lane = tid & 31, wid = tid >> 5;
    for (int c = wid; c < N; c += NWARPS) {
        float4 x = *(const float4*)(q + c * DIM + lane * 4);
        float m = fmaxf(fmaxf(x.x, x.y), fmaxf(x.z, x.w));
        m = fmaxf(m, __shfl_xor_sync(0xffffffffu, m, 1));
        m = fmaxf(m, __shfl_xor_sync(0xffffffffu, m, 2));
        float4 e;
        e.x = expf(x.x - m); e.y = expf(x.y - m);
        e.z = expf(x.z - m); e.w = expf(x.w - m);
        float s = e.x + e.y + e.z + e.w;
        s += __shfl_xor_sync(0xffffffffu, s, 1);
        s += __shfl_xor_sync(0xffffffffu, s, 2);
        float sc = 0.25f / s;
        e.x *= sc; e.y *= sc; e.z *= sc; e.w *= sc;
        *(float4*)(q + c * DIM + lane * 4) = e;
    }
}

// softmax over the sequence dim (per feature column)
template<int N>
__device__ __forceinline__ void softmax_seq(float* __restrict__ k, int tid)
{
    if (tid < DIM) {
        float* p = k + tid;
        float m = -1e30f;
        for (int c = 0; c < N; c++) m = fmaxf(m, p[c * DIM]);
        float s = 0.f;
        for (int c = 0; c < N; c++) {
            float e = expf(p[c * DIM] - m);
            p[c * DIM] = e;
            s += e;
        }
        float inv = 1.0f / s;
        for (int c = 0; c < N; c++) p[c * DIM] *= inv;
    }
}

// ctx[h][d][e] = sum_c k[c][h*16+d] * v[c][h*16+e]
template<int N>
__device__ __forceinline__ void compute_ctx(
    const float* __restrict__ k, const float* __restrict__ v,
    float* __restrict__ ctx, int tid)
{
    for (int o = tid; o < HEADS * DH * DH; o += NTHREADS) {
        int hh = o >> 8, d = (o >> 4) & 15, e = o & 15;
        const float* kp = k + hh * DH + d;
        const float* vp = v + hh * DH + e;
        float a = 0.f;
        for (int c = 0; c < N; c++) a += kp[c * DIM] * vp[c * DIM];
        ctx[o] = a;
    }
}

// o[c][h*16+e] = sum_d q[c][h*16+d] * ctx[h][d][e]
template<int N>
__device__ __forceinline__ void apply_ctx(
    const float* __restrict__ q, const float* __restrict__ ctx,
    float* __restrict__ o, int tid)
{
    int tx = tid & 31, ty = tid >> 5;
    int hh = tx >> 2;
    int ecol = (tx & 3) * 4;
    for (int c = ty; c < N; c += NWARPS) {
        float4 acc = make_float4(0.f, 0.f, 0.f, 0.f);
        const float* qp = q + c * DIM + hh * DH;
        const float* cp = ctx + hh * DH * DH + ecol;
#pragma unroll
        for (int d = 0; d < DH; d++) {
            float qv = qp[d];
            float4 cv = *(const float4*)(cp + d * DH);
            acc.x += qv * cv.x; acc.y += qv * cv.y;
            acc.z += qv * cv.z; acc.w += qv * cv.w;
        }
        *(float4*)(o + c * DIM + tx * 4) = acc;
    }
}

template<int N>
__device__ __forceinline__ void mean_rows(
    const float* __restrict__ h, float* __restrict__ out, int tid)
{
    if (tid < DIM) {
        float s = 0.f;
        for (int c = 0; c < N; c++) s += h[c * DIM + tid];
        out[tid] = s * (1.0f / N);
    }
}

// ---------------------------------------------------------------------------
// One CTA = one sequence. Full 4-layer stack in SMEM.
// SMEM: h | s1 | s2 | s3 | s4 | s5 | ctx(2048) | wbuf(2*16*128)
//   attn: xn->s1, q->s2, k->s3, v->s4, o->s1 (reuse)
//   ff:   xn2->s5, t[N][512] spans s1..s4 (contiguous)
// MODE 0: channel stack, load from x [B,E,C,P], write mean -> g_mid[s]
// MODE 1: temporal stack, load from g_mid, write mean -> gout[b]
// ---------------------------------------------------------------------------
template<int N, int MODE>
__global__ void __launch_bounds__(NTHREADS, 1)
stack_kernel(const float* __restrict__ xin, float* __restrict__ gout, StackParams P)
{
    extern __shared__ float sm[];
    float* h    = sm;
    float* s1   = sm + N * DIM;
    float* s2   = s1 + N * DIM;
    float* s3   = s2 + N * DIM;
    float* s4   = s3 + N * DIM;
    float* s5   = s4 + N * DIM;
    float* ctx  = s5 + N * DIM;
    float* wbuf = ctx + HEADS * DH * DH;

    const int tid = threadIdx.x;

    // -------- load sequence into h --------
    if (MODE == 0) {
        int s = blockIdx.x;
        int b = s >> 6, p = s & 63;
        const float* xb = xin + (size_t)b * DIM * 62 * 64 + p;
        for (int i = tid; i < N * DIM; i += NTHREADS) {
            int c = i >> 7, e = i & 127;
            h[i] = xb[(e * 62 + c) * 64];
        }
    } else {
        const float* xb = g_mid + (size_t)blockIdx.x * N * DIM;
        for (int i = tid; i < N * DIM; i += NTHREADS) h[i] = xb[i];
    }
    __syncthreads();

    for (int l = 0; l < DEPTH; l++) {
        const float* Wq  = P.Wq  + l * DIM * DIM;
        const float* Wk  = P.Wk  + l * DIM * DIM;
        const float* Wv  = P.Wv  + l * DIM * DIM;
        const float* Wo  = P.Wo  + l * DIM * DIM;
        const float* bo  = P.bo  + l * DIM;
        const float* g1  = P.g1  + l * DIM;
        const float* be1 = P.be1 + l * DIM;
        const float* g2  = P.g2  + l * DIM;
        const float* be2 = P.be2 + l * DIM;
        const float* W1  = P.W1  + l * DIM * FFD;
        const float* bf1 = P.bf1 + l * FFD;
        const float* W2  = P.W2  + l * FFD * DIM;
        const float* bf2 = P.bf2 + l * DIM;

        // ---- attention ----
        layernorm<N>(h, s1, g1, be1, tid);
        __syncthreads();

        gemm_staged<N, DIM, false, false, false>(s1, DIM, Wq, DIM, nullptr, s2, DIM, wbuf, tid);
        gemm_staged<N, DIM, false, false, false>(s1, DIM, Wk, DIM, nullptr, s3, DIM, wbuf, tid);
        gemm_staged<N, DIM, false, false, false>(s1, DIM, Wv, DIM, nullptr, s4, DIM, wbuf, tid);

        softmax_feat<N>(s2, tid);
        softmax_seq<N>(s3, tid);
        __syncthreads();

        compute_ctx<N>(s3, s4, ctx, tid);
        __syncthreads();

        apply_ctx<N>(s2, ctx, s1, tid);
        __syncthreads();

        gemm_staged<N, DIM, true, false, true>(s1, DIM, Wo, DIM, bo, h, DIM, wbuf, tid);

        // ---- feed-forward ----
        layernorm<N>(h, s5, g2, be2, tid);
        __syncthreads();

#pragma unroll
        for (int j = 0; j < 4; j++) {
            gemm_staged<N, DIM, false, true, true>(s5, DIM,
                                                   W1 + j * DIM, FFD,
                                                   bf1 + j * DIM,
                                                   s1 + j * DIM, FFD, wbuf, tid);
        }

        gemm_staged<N, FFD, true, false, true>(s1, FFD, W2, DIM, bf2, h, DIM, wbuf, tid);
    }

    // -------- mean over tokens --------
    if (MODE == 0) {
        mean_rows<N>(h, g_mid + (size_t)blockIdx.x * DIM, tid);
    } else {
        mean_rows<N>(h, gout + (size_t)blockIdx.x * DIM, tid);
    }
}

// ---------------------------------------------------------------------------
static StackParams mk_params(void* const* d_in, int base)
{
    StackParams p;
    p.Wq  = (const float*)d_in[base + 0];
    p.Wk  = (const float*)d_in[base + 1];
    p.Wv  = (const float*)d_in[base + 2];
    p.Wo  = (const float*)d_in[base + 3];
    p.bo  = (const float*)d_in[base + 4];
    p.g1  = (const float*)d_in[base + 5];
    p.be1 = (const float*)d_in[base + 6];
    p.g2  = (const float*)d_in[base + 7];
    p.be2 = (const float*)d_in[base + 8];
    p.W1  = (const float*)d_in[base + 9];
    p.bf1 = (const float*)d_in[base + 10];
    p.W2  = (const float*)d_in[base + 11];
    p.bf2 = (const float*)d_in[base + 12];
    return p;
}

extern "C" void kernel_launch(void* const* d_in, const int* in_sizes, int n_in,
                              void* d_out, int out_size)
{
    (void)in_sizes; (void)n_in; (void)out_size;

    const float* x = (const float*)d_in[0];
    StackParams Pc = mk_params(d_in, 1);
    StackParams Pt = mk_params(d_in, 14);

    const int SMEM_A = (6 * 62 * DIM + HEADS * DH * DH + WBUF_ELEMS) * (int)sizeof(float); // 215040
    const int SMEM_B = (6 * 64 * DIM + HEADS * DH * DH + WBUF_ELEMS) * (int)sizeof(float); // 221184

    cudaFuncSetAttribute(stack_kernel<62, 0>,
                         cudaFuncAttributeMaxDynamicSharedMemorySize, SMEM_A);
    cudaFuncSetAttribute(stack_kernel<64, 1>,
                         cudaFuncAttributeMaxDynamicSharedMemorySize, SMEM_B);

    // channel stack: 64 batches * 64 patches sequences of length 62
    stack_kernel<62, 0><<<4096, NTHREADS, SMEM_A>>>(x, nullptr, Pc);
    // temporal stack: 64 sequences of length 64 (reads g_mid, writes d_out)
    stack_kernel<64, 1><<<64, NTHREADS, SMEM_B>>>(nullptr, (float*)d_out, Pt);
}